// round 12
// baseline (speedup 1.0000x reference)
#include <cuda_runtime.h>

#define NB   4
#define SEQ  4096
#define ED   1024
#define VOC  32000
#define QKV3 3072

__device__ __forceinline__ size_t tok(const int* __restrict__ x, size_t i) {
    unsigned v = (unsigned)x[i];
    return (size_t)(v < VOC ? v : VOC - 1);
}

// ---------------- scratch ----------------
__device__ float g_qpart[NB][16][ED];    // partial q over e-chunks of 64
__device__ float g_q[NB][ED];            // q + bq
__device__ float g_qt[NB][ED];           // q~ = Wk @ q
__device__ float g_part[NB][128][ED];    // partial unnormalized hbar (j-chunks of 32)
__device__ float g_psum[NB][128];        // partial sums of exp weights
__device__ float g_hbar[NB][ED];         // normalized attention-weighted embed sum
__device__ float g_hfpart[NB][16][ED];   // partial hbar @ Wv (e-chunks of 64)
__device__ float g_opart[8][NB][VOC];    // partial output logits (e-chunks of 128)

// ---------------- K1: partial q[d], batch-merged (Wq read ONCE) ----------------
// grid(64) = ec16 x dc4, 256 threads
__global__ void k1_qpart(const int* __restrict__ x,
                         const float* __restrict__ embed,
                         const float* __restrict__ qkv_w) {
    int ec = blockIdx.x & 15, dc = blockIdx.x >> 4;
    int t = threadIdx.x;
    __shared__ float sh[NB][64];
    {
        int b = t >> 6, el = t & 63;
        sh[b][el] = embed[tok(x, (size_t)b * SEQ + SEQ - 1) * ED + ec * 64 + el];
    }
    __syncthreads();
    int d = dc * 256 + t;
    const float* w = qkv_w + (size_t)(ec * 64) * QKV3 + d;   // Wq
    float a0 = 0.f, a1 = 0.f, a2 = 0.f, a3 = 0.f;
    #pragma unroll 16
    for (int e = 0; e < 64; e++) {
        float wv = w[(size_t)e * QKV3];
        a0 = fmaf(sh[0][e], wv, a0);
        a1 = fmaf(sh[1][e], wv, a1);
        a2 = fmaf(sh[2][e], wv, a2);
        a3 = fmaf(sh[3][e], wv, a3);
    }
    g_qpart[0][ec][d] = a0; g_qpart[1][ec][d] = a1;
    g_qpart[2][ec][d] = a2; g_qpart[3][ec][d] = a3;
}

// ---------------- K1r: q = sum partials + bq ----------------
__global__ void k1r(const float* __restrict__ qkv_b) {
    int b = blockIdx.x, d = threadIdx.x;
    float a = qkv_b[d];
    #pragma unroll
    for (int c = 0; c < 16; c++) a += g_qpart[b][c][d];
    g_q[b][d] = a;
}

// ---------------- K1b: q~ = Wk @ q, batch-merged (Wk read ONCE) ----------------
// grid(128), 256 threads (8 warps, 1 Wk row per warp)
__global__ void k1b_qt(const float* __restrict__ qkv_w) {
    int warp = threadIdx.x >> 5, lane = threadIdx.x & 31;
    __shared__ float4 sq[NB][256];
    for (int i = threadIdx.x; i < NB * 256; i += 256)
        sq[i >> 8][i & 255] = ((const float4*)g_q[i >> 8])[i & 255];
    __syncthreads();
    int e = blockIdx.x * 8 + warp;
    const float4* w4 = (const float4*)(qkv_w + (size_t)e * QKV3 + ED);  // Wk row e
    float d0 = 0.f, d1 = 0.f, d2 = 0.f, d3 = 0.f;
    #pragma unroll 4
    for (int i = lane; i < 256; i += 32) {
        float4 w = w4[i];
        float4 q0 = sq[0][i], q1 = sq[1][i], q2 = sq[2][i], q3 = sq[3][i];
        d0 += w.x * q0.x + w.y * q0.y + w.z * q0.z + w.w * q0.w;
        d1 += w.x * q1.x + w.y * q1.y + w.z * q1.z + w.w * q1.w;
        d2 += w.x * q2.x + w.y * q2.y + w.z * q2.z + w.w * q2.w;
        d3 += w.x * q3.x + w.y * q3.y + w.z * q3.z + w.w * q3.w;
    }
    #pragma unroll
    for (int o = 16; o; o >>= 1) {
        d0 += __shfl_xor_sync(0xffffffffu, d0, o);
        d1 += __shfl_xor_sync(0xffffffffu, d1, o);
        d2 += __shfl_xor_sync(0xffffffffu, d2, o);
        d3 += __shfl_xor_sync(0xffffffffu, d3, o);
    }
    if (!lane) {
        g_qt[0][e] = d0; g_qt[1][e] = d1; g_qt[2][e] = d2; g_qt[3][e] = d3;
    }
}

// ---------------- JFUSE: logits + exp + weighted-embed accumulate, one gather pass ----------------
// grid (128, NB), 256 threads (8 warps), 32 j per block, 4 j per warp
__global__ void jfuse(const int* __restrict__ x,
                      const float* __restrict__ embed) {
    int b = blockIdx.y, chunk = blockIdx.x;
    int warp = threadIdx.x >> 5, lane = threadIdx.x & 31;
    __shared__ float4 sq4[256];        // q~
    __shared__ float sred[8][ED];      // 32KB per-warp partials
    __shared__ float spsum[8];
    for (int i = threadIdx.x; i < 256; i += 256) sq4[i] = ((const float4*)g_qt[b])[i];
    __syncthreads();

    float4 acc[8];
    #pragma unroll
    for (int i = 0; i < 8; i++) acc[i] = make_float4(0.f, 0.f, 0.f, 0.f);
    float wsum = 0.f;

    #pragma unroll
    for (int jj = 0; jj < 4; jj++) {
        int j = chunk * 32 + warp * 4 + jj;
        const float4* r4 = (const float4*)(embed + tok(x, (size_t)b * SEQ + j) * ED);
        float4 row[8];
        float dot = 0.f;
        #pragma unroll
        for (int i = 0; i < 8; i++) {
            row[i] = r4[lane + 32 * i];
            float4 q = sq4[lane + 32 * i];
            dot += row[i].x * q.x + row[i].y * q.y + row[i].z * q.z + row[i].w * q.w;
        }
        #pragma unroll
        for (int o = 16; o; o >>= 1) dot += __shfl_xor_sync(0xffffffffu, dot, o);
        float wj = expf(dot * 0.03125f);      // shift-invariant softmax: no max-sub needed
        wsum += wj;
        #pragma unroll
        for (int i = 0; i < 8; i++) {
            acc[i].x = fmaf(wj, row[i].x, acc[i].x);
            acc[i].y = fmaf(wj, row[i].y, acc[i].y);
            acc[i].z = fmaf(wj, row[i].z, acc[i].z);
            acc[i].w = fmaf(wj, row[i].w, acc[i].w);
        }
    }
    float4* myred = (float4*)sred[warp];
    #pragma unroll
    for (int i = 0; i < 8; i++) myred[lane + 32 * i] = acc[i];
    if (!lane) spsum[warp] = wsum;
    __syncthreads();
    for (int p = threadIdx.x; p < ED; p += 256) {
        float s = 0.f;
        #pragma unroll
        for (int w = 0; w < 8; w++) s += sred[w][p];
        g_part[b][chunk][p] = s;
    }
    if (threadIdx.x == 0) {
        float s = 0.f;
        #pragma unroll
        for (int w = 0; w < 8; w++) s += spsum[w];
        g_psum[b][chunk] = s;
    }
}

// ---------------- K4b: hbar = (sum_j partials) / (sum exp) ----------------
// grid(NB), 1024 threads — UNIFORM barrier flow (no divergent __syncthreads)
__global__ void k4b_hbar() {
    int b = blockIdx.x, d = threadIdx.x;
    __shared__ float ws[32];
    __shared__ float stot;
    // all threads participate: lanes holding no psum contribute 0
    float v = (d < 128) ? g_psum[b][d] : 0.f;
    #pragma unroll
    for (int o = 16; o; o >>= 1) v += __shfl_xor_sync(0xffffffffu, v, o);
    if ((d & 31) == 0) ws[d >> 5] = v;
    __syncthreads();
    if (d == 0) {
        float s = 0.f;
        #pragma unroll
        for (int w = 0; w < 4; w++) s += ws[w];   // only warps 0-3 held data
        stot = s;
    }
    float a = 0.f;
    #pragma unroll 8
    for (int c = 0; c < 128; c++) a += g_part[b][c][d];
    __syncthreads();
    g_hbar[b][d] = a / stot;
}

// ---------------- K5: partial hbar@Wv, batch-merged (Wv read ONCE) ----------------
// grid(64) = ec16 x dc4, 256 threads
__global__ void k5_part(const float* __restrict__ qkv_w) {
    int ec = blockIdx.x & 15, dc = blockIdx.x >> 4;
    int t = threadIdx.x;
    __shared__ float sh[NB][64];
    {
        int b = t >> 6, el = t & 63;
        sh[b][el] = g_hbar[b][ec * 64 + el];
    }
    __syncthreads();
    int d = dc * 256 + t;
    const float* w = qkv_w + (size_t)(ec * 64) * QKV3 + 2048 + d;  // Wv
    float a0 = 0.f, a1 = 0.f, a2 = 0.f, a3 = 0.f;
    #pragma unroll 16
    for (int e = 0; e < 64; e++) {
        float wv = w[(size_t)e * QKV3];
        a0 = fmaf(sh[0][e], wv, a0);
        a1 = fmaf(sh[1][e], wv, a1);
        a2 = fmaf(sh[2][e], wv, a2);
        a3 = fmaf(sh[3][e], wv, a3);
    }
    g_hfpart[0][ec][d] = a0; g_hfpart[1][ec][d] = a1;
    g_hfpart[2][ec][d] = a2; g_hfpart[3][ec][d] = a3;
}

// ---------------- K6: build hf slice (reduce + bv + residual) then vocab GEMV partial ----------------
// grid (63, 8), 128 threads
__global__ void k6_part(const float* __restrict__ out_w,
                        const float* __restrict__ qkv_b,
                        const int* __restrict__ x,
                        const float* __restrict__ embed) {
    int ecb = blockIdx.y;                 // e-chunk of 128
    int tid = threadIdx.x;
    __shared__ float sh[NB][128];
    int e = ecb * 128 + tid;
    #pragma unroll
    for (int b = 0; b < NB; b++) {
        float a = qkv_b[2048 + e];
        #pragma unroll
        for (int c = 0; c < 16; c++) a += g_hfpart[b][c][e];
        a += embed[tok(x, (size_t)b * SEQ + SEQ - 1) * ED + e];
        sh[b][tid] = a;
    }
    __syncthreads();
    int vt = blockIdx.x * 512 + tid * 4;
    if (vt >= VOC) return;
    float4 a0 = {0,0,0,0}, a1 = a0, a2 = a0, a3 = a0;
    const float* base = out_w + (size_t)(ecb * 128) * VOC + vt;
    #pragma unroll 8
    for (int ee = 0; ee < 128; ee++) {
        float4 w = *(const float4*)(base + (size_t)ee * VOC);
        float h0 = sh[0][ee], h1 = sh[1][ee], h2 = sh[2][ee], h3 = sh[3][ee];
        a0.x = fmaf(h0, w.x, a0.x); a0.y = fmaf(h0, w.y, a0.y);
        a0.z = fmaf(h0, w.z, a0.z); a0.w = fmaf(h0, w.w, a0.w);
        a1.x = fmaf(h1, w.x, a1.x); a1.y = fmaf(h1, w.y, a1.y);
        a1.z = fmaf(h1, w.z, a1.z); a1.w = fmaf(h1, w.w, a1.w);
        a2.x = fmaf(h2, w.x, a2.x); a2.y = fmaf(h2, w.y, a2.y);
        a2.z = fmaf(h2, w.z, a2.z); a2.w = fmaf(h2, w.w, a2.w);
        a3.x = fmaf(h3, w.x, a3.x); a3.y = fmaf(h3, w.y, a3.y);
        a3.z = fmaf(h3, w.z, a3.z); a3.w = fmaf(h3, w.w, a3.w);
    }
    *(float4*)(&g_opart[ecb][0][vt]) = a0;
    *(float4*)(&g_opart[ecb][1][vt]) = a1;
    *(float4*)(&g_opart[ecb][2][vt]) = a2;
    *(float4*)(&g_opart[ecb][3][vt]) = a3;
}

// ---------------- K6b: final reduce ----------------
__global__ void k6b_red(const float* __restrict__ out_b,
                        float* __restrict__ out) {
    int b = blockIdx.y;
    int v = blockIdx.x * 256 + threadIdx.x;       // 125*256 = 32000 exactly
    float a = out_b[v];
    #pragma unroll
    for (int c = 0; c < 8; c++) a += g_opart[c][b][v];
    out[(size_t)b * VOC + v] = a;
}

// ---------------- launch ----------------
extern "C" void kernel_launch(void* const* d_in, const int* in_sizes, int n_in,
                              void* d_out, int out_size) {
    const int* x           = (const int*)d_in[0];
    const float* embed     = (const float*)d_in[1];
    const float* qkv_w     = (const float*)d_in[2];
    const float* qkv_b     = (const float*)d_in[3];
    const float* out_w     = (const float*)d_in[4];
    const float* out_b     = (const float*)d_in[5];
    float* out             = (float*)d_out;

    k1_qpart <<<dim3(64),      256>>>(x, embed, qkv_w);
    k1r      <<<dim3(NB),      1024>>>(qkv_b);
    k1b_qt   <<<dim3(128),     256>>>(qkv_w);
    jfuse    <<<dim3(128, NB), 256>>>(x, embed);
    k4b_hbar <<<dim3(NB),      1024>>>();
    k5_part  <<<dim3(64),      256>>>(qkv_w);
    k6_part  <<<dim3(63, 8),   128>>>(out_w, qkv_b, x, embed);
    k6b_red  <<<dim3(125, NB), 256>>>(out_b, out);
}

// round 14
// speedup vs baseline: 1.0995x; 1.0995x over previous
#include <cuda_runtime.h>

#define NB   4
#define SEQ  4096
#define ED   1024
#define VOC  32000
#define QKV3 3072

__device__ __forceinline__ size_t tok(const int* __restrict__ x, size_t i) {
    unsigned v = (unsigned)x[i];
    return (size_t)(v < VOC ? v : VOC - 1);
}

// ---------------- scratch ----------------
__device__ float g_qpart[NB][16][ED];    // partial q over e-chunks of 64
__device__ float g_q[NB][ED];            // q + bq
__device__ float g_qt[NB][ED];           // q~ = Wk @ q
__device__ float g_part[NB][512][ED];    // per-warp unnormalized hbar partials (8 j each)
__device__ float g_psum[NB][512];        // per-warp exp-weight sums
__device__ float g_hbar[NB][ED];         // normalized attention-weighted embed sum
__device__ float g_hfpart[NB][16][ED];   // partial hbar @ Wv (e-chunks of 64)
__device__ float g_opart[16][NB][VOC];   // partial output logits (e-chunks of 64)

// ---------------- K1: partial q[d], batch-merged (Wq read ONCE) ----------------
// grid(64) = ec16 x dc4, 256 threads
__global__ void k1_qpart(const int* __restrict__ x,
                         const float* __restrict__ embed,
                         const float* __restrict__ qkv_w) {
    int ec = blockIdx.x & 15, dc = blockIdx.x >> 4;
    int t = threadIdx.x;
    __shared__ float sh[NB][64];
    {
        int b = t >> 6, el = t & 63;
        sh[b][el] = embed[tok(x, (size_t)b * SEQ + SEQ - 1) * ED + ec * 64 + el];
    }
    __syncthreads();
    int d = dc * 256 + t;
    const float* w = qkv_w + (size_t)(ec * 64) * QKV3 + d;   // Wq
    float a0 = 0.f, a1 = 0.f, a2 = 0.f, a3 = 0.f;
    #pragma unroll 16
    for (int e = 0; e < 64; e++) {
        float wv = w[(size_t)e * QKV3];
        a0 = fmaf(sh[0][e], wv, a0);
        a1 = fmaf(sh[1][e], wv, a1);
        a2 = fmaf(sh[2][e], wv, a2);
        a3 = fmaf(sh[3][e], wv, a3);
    }
    g_qpart[0][ec][d] = a0; g_qpart[1][ec][d] = a1;
    g_qpart[2][ec][d] = a2; g_qpart[3][ec][d] = a3;
}

// ---------------- K1r: q = sum partials + bq ----------------
__global__ void k1r(const float* __restrict__ qkv_b) {
    int b = blockIdx.x, d = threadIdx.x;
    float a = qkv_b[d];
    #pragma unroll
    for (int c = 0; c < 16; c++) a += g_qpart[b][c][d];
    g_q[b][d] = a;
}

// ---------------- K1b: q~ = Wk @ q, batch-merged (Wk read ONCE) ----------------
// grid(128), 256 threads (8 warps, 1 Wk row per warp)
__global__ void k1b_qt(const float* __restrict__ qkv_w) {
    int warp = threadIdx.x >> 5, lane = threadIdx.x & 31;
    __shared__ float4 sq[NB][256];
    for (int i = threadIdx.x; i < NB * 256; i += 256)
        sq[i >> 8][i & 255] = ((const float4*)g_q[i >> 8])[i & 255];
    __syncthreads();
    int e = blockIdx.x * 8 + warp;
    const float4* w4 = (const float4*)(qkv_w + (size_t)e * QKV3 + ED);  // Wk row e
    float d0 = 0.f, d1 = 0.f, d2 = 0.f, d3 = 0.f;
    #pragma unroll 4
    for (int i = lane; i < 256; i += 32) {
        float4 w = w4[i];
        float4 q0 = sq[0][i], q1 = sq[1][i], q2 = sq[2][i], q3 = sq[3][i];
        d0 += w.x * q0.x + w.y * q0.y + w.z * q0.z + w.w * q0.w;
        d1 += w.x * q1.x + w.y * q1.y + w.z * q1.z + w.w * q1.w;
        d2 += w.x * q2.x + w.y * q2.y + w.z * q2.z + w.w * q2.w;
        d3 += w.x * q3.x + w.y * q3.y + w.z * q3.z + w.w * q3.w;
    }
    #pragma unroll
    for (int o = 16; o; o >>= 1) {
        d0 += __shfl_xor_sync(0xffffffffu, d0, o);
        d1 += __shfl_xor_sync(0xffffffffu, d1, o);
        d2 += __shfl_xor_sync(0xffffffffu, d2, o);
        d3 += __shfl_xor_sync(0xffffffffu, d3, o);
    }
    if (!lane) {
        g_qt[0][e] = d0; g_qt[1][e] = d1; g_qt[2][e] = d2; g_qt[3][e] = d3;
    }
}

// ---------------- JFUSE: logits + exp + weighted-embed accumulate, one gather pass ----------------
// grid (64, NB), 256 threads (8 warps), 8 j per warp, per-warp partial straight to global
__global__ void __launch_bounds__(256, 2)
jfuse(const int* __restrict__ x, const float* __restrict__ embed) {
    int b = blockIdx.y, chunk = blockIdx.x;
    int warp = threadIdx.x >> 5, lane = threadIdx.x & 31;
    __shared__ float4 sq4[256];        // q~ only: 4KB smem
    for (int i = threadIdx.x; i < 256; i += 256) sq4[i] = ((const float4*)g_qt[b])[i];
    __syncthreads();

    float4 acc[8];
    #pragma unroll
    for (int i = 0; i < 8; i++) acc[i] = make_float4(0.f, 0.f, 0.f, 0.f);
    float wsum = 0.f;

    #pragma unroll
    for (int jj = 0; jj < 8; jj++) {
        int j = chunk * 64 + warp * 8 + jj;
        const float4* r4 = (const float4*)(embed + tok(x, (size_t)b * SEQ + j) * ED);
        float4 row[8];
        float dot = 0.f;
        #pragma unroll
        for (int i = 0; i < 8; i++) {
            row[i] = r4[lane + 32 * i];
            float4 q = sq4[lane + 32 * i];
            dot += row[i].x * q.x + row[i].y * q.y + row[i].z * q.z + row[i].w * q.w;
        }
        #pragma unroll
        for (int o = 16; o; o >>= 1) dot += __shfl_xor_sync(0xffffffffu, dot, o);
        float wj = expf(dot * 0.03125f);      // shift-invariant softmax: no max-sub needed
        wsum += wj;
        #pragma unroll
        for (int i = 0; i < 8; i++) {
            acc[i].x = fmaf(wj, row[i].x, acc[i].x);
            acc[i].y = fmaf(wj, row[i].y, acc[i].y);
            acc[i].z = fmaf(wj, row[i].z, acc[i].z);
            acc[i].w = fmaf(wj, row[i].w, acc[i].w);
        }
    }
    int wc = chunk * 8 + warp;                 // warp-chunk id 0..511
    float4* dst = (float4*)g_part[b][wc];
    #pragma unroll
    for (int i = 0; i < 8; i++) dst[lane + 32 * i] = acc[i];
    if (!lane) g_psum[b][wc] = wsum;           // wsum identical across lanes
}

// ---------------- K4b: hbar = (sum_j partials) / (sum exp); UNIFORM barriers ----------------
// grid(NB), 1024 threads
__global__ void k4b_hbar() {
    int b = blockIdx.x, d = threadIdx.x;
    __shared__ float ws[32];
    __shared__ float stot;
    float v = (d < 512) ? g_psum[b][d] : 0.f;
    #pragma unroll
    for (int o = 16; o; o >>= 1) v += __shfl_xor_sync(0xffffffffu, v, o);
    if ((d & 31) == 0) ws[d >> 5] = v;
    __syncthreads();
    if (d == 0) {
        float s = 0.f;
        #pragma unroll
        for (int w = 0; w < 16; w++) s += ws[w];   // warps 0-15 held psum data
        stot = s;
    }
    float a = 0.f;
    #pragma unroll 16
    for (int c = 0; c < 512; c++) a += g_part[b][c][d];
    __syncthreads();
    g_hbar[b][d] = a / stot;
}

// ---------------- K5: partial hbar@Wv, batch-merged (Wv read ONCE) ----------------
// grid(64) = ec16 x dc4, 256 threads
__global__ void k5_part(const float* __restrict__ qkv_w) {
    int ec = blockIdx.x & 15, dc = blockIdx.x >> 4;
    int t = threadIdx.x;
    __shared__ float sh[NB][64];
    {
        int b = t >> 6, el = t & 63;
        sh[b][el] = g_hbar[b][ec * 64 + el];
    }
    __syncthreads();
    int d = dc * 256 + t;
    const float* w = qkv_w + (size_t)(ec * 64) * QKV3 + 2048 + d;  // Wv
    float a0 = 0.f, a1 = 0.f, a2 = 0.f, a3 = 0.f;
    #pragma unroll 16
    for (int e = 0; e < 64; e++) {
        float wv = w[(size_t)e * QKV3];
        a0 = fmaf(sh[0][e], wv, a0);
        a1 = fmaf(sh[1][e], wv, a1);
        a2 = fmaf(sh[2][e], wv, a2);
        a3 = fmaf(sh[3][e], wv, a3);
    }
    g_hfpart[0][ec][d] = a0; g_hfpart[1][ec][d] = a1;
    g_hfpart[2][ec][d] = a2; g_hfpart[3][ec][d] = a3;
}

// ---------------- K6: build hf slice then vocab GEMV partial over 64-e chunk ----------------
// grid (63, 16), 128 threads
__global__ void k6_part(const float* __restrict__ out_w,
                        const float* __restrict__ qkv_b,
                        const int* __restrict__ x,
                        const float* __restrict__ embed) {
    int ecb = blockIdx.y;                 // e-chunk of 64
    int tid = threadIdx.x;
    __shared__ float sh[NB][64];
    for (int i = tid; i < NB * 64; i += 128) {
        int b = i >> 6, el = i & 63;
        int e = ecb * 64 + el;
        float a = qkv_b[2048 + e];
        #pragma unroll
        for (int c = 0; c < 16; c++) a += g_hfpart[b][c][e];
        a += embed[tok(x, (size_t)b * SEQ + SEQ - 1) * ED + e];
        sh[b][el] = a;
    }
    __syncthreads();
    int vt = blockIdx.x * 512 + tid * 4;
    if (vt >= VOC) return;
    float4 a0 = {0,0,0,0}, a1 = a0, a2 = a0, a3 = a0;
    const float* base = out_w + (size_t)(ecb * 64) * VOC + vt;
    #pragma unroll 8
    for (int ee = 0; ee < 64; ee++) {
        float4 w = *(const float4*)(base + (size_t)ee * VOC);
        float h0 = sh[0][ee], h1 = sh[1][ee], h2 = sh[2][ee], h3 = sh[3][ee];
        a0.x = fmaf(h0, w.x, a0.x); a0.y = fmaf(h0, w.y, a0.y);
        a0.z = fmaf(h0, w.z, a0.z); a0.w = fmaf(h0, w.w, a0.w);
        a1.x = fmaf(h1, w.x, a1.x); a1.y = fmaf(h1, w.y, a1.y);
        a1.z = fmaf(h1, w.z, a1.z); a1.w = fmaf(h1, w.w, a1.w);
        a2.x = fmaf(h2, w.x, a2.x); a2.y = fmaf(h2, w.y, a2.y);
        a2.z = fmaf(h2, w.z, a2.z); a2.w = fmaf(h2, w.w, a2.w);
        a3.x = fmaf(h3, w.x, a3.x); a3.y = fmaf(h3, w.y, a3.y);
        a3.z = fmaf(h3, w.z, a3.z); a3.w = fmaf(h3, w.w, a3.w);
    }
    *(float4*)(&g_opart[ecb][0][vt]) = a0;
    *(float4*)(&g_opart[ecb][1][vt]) = a1;
    *(float4*)(&g_opart[ecb][2][vt]) = a2;
    *(float4*)(&g_opart[ecb][3][vt]) = a3;
}

// ---------------- K6b: final reduce ----------------
__global__ void k6b_red(const float* __restrict__ out_b,
                        float* __restrict__ out) {
    int b = blockIdx.y;
    int v = blockIdx.x * 256 + threadIdx.x;       // 125*256 = 32000 exactly
    float a = out_b[v];
    #pragma unroll
    for (int c = 0; c < 16; c++) a += g_opart[c][b][v];
    out[(size_t)b * VOC + v] = a;
}

// ---------------- launch ----------------
extern "C" void kernel_launch(void* const* d_in, const int* in_sizes, int n_in,
                              void* d_out, int out_size) {
    const int* x           = (const int*)d_in[0];
    const float* embed     = (const float*)d_in[1];
    const float* qkv_w     = (const float*)d_in[2];
    const float* qkv_b     = (const float*)d_in[3];
    const float* out_w     = (const float*)d_in[4];
    const float* out_b     = (const float*)d_in[5];
    float* out             = (float*)d_out;

    k1_qpart <<<dim3(64),      256>>>(x, embed, qkv_w);
    k1r      <<<dim3(NB),      1024>>>(qkv_b);
    k1b_qt   <<<dim3(128),     256>>>(qkv_w);
    jfuse    <<<dim3(64, NB),  256>>>(x, embed);
    k4b_hbar <<<dim3(NB),      1024>>>();
    k5_part  <<<dim3(64),      256>>>(qkv_w);
    k6_part  <<<dim3(63, 16),  128>>>(out_w, qkv_b, x, embed);
    k6b_red  <<<dim3(125, NB), 256>>>(out_b, out);
}